// round 8
// baseline (speedup 1.0000x reference)
#include <cuda_runtime.h>

// Contour_to_mask via winding angles.
// angle_k = acos(clip(dot/(|d||r|), ±(1-1e-5))) == clamp(atan2(|cr|,dot), A0, pi-A0)
// atan2(A,D) for A,D>=0 == pi/4 + atan((A-D)/(A+D))   [exact Pade rotation]
// => angle = pi/2 - copysign(min(pi/4 - atan(r), UMAX), dot)
// sign_k = tanh(K*cr);  out = min(|sum_k sign_k*angle_k|/2pi, 1)
//
// Coords prescaled by sqrt(K); 2 px/thread; geometry + atan poly packed f32x2.

#define MSIZE   256
#define KV      64
#define NCONT   8

#define SQRTK   316.2277660168379f
#define XSC     1.2352647109f          /* SQRTK / 256 */

typedef unsigned long long ull;

__device__ __forceinline__ ull pk(float lo, float hi) {
    ull r; asm("mov.b64 %0, {%1,%2};" : "=l"(r) : "f"(lo), "f"(hi)); return r;
}
__device__ __forceinline__ void upk(float& lo, float& hi, ull v) {
    asm("mov.b64 {%0,%1}, %2;" : "=f"(lo), "=f"(hi) : "l"(v));
}
__device__ __forceinline__ ull f2add(ull a, ull b) {
    ull d; asm("add.rn.f32x2 %0,%1,%2;" : "=l"(d) : "l"(a), "l"(b)); return d;
}
__device__ __forceinline__ ull f2mul(ull a, ull b) {
    ull d; asm("mul.rn.f32x2 %0,%1,%2;" : "=l"(d) : "l"(a), "l"(b)); return d;
}
__device__ __forceinline__ ull f2fma(ull a, ull b, ull c) {
    ull d; asm("fma.rn.f32x2 %0,%1,%2,%3;" : "=l"(d) : "l"(a), "l"(b), "l"(c)); return d;
}
__device__ __forceinline__ float frcp(float x) {
    float r; asm("rcp.approx.f32 %0,%1;" : "=f"(r) : "f"(x)); return r;
}
__device__ __forceinline__ float ftanh(float x) {
    float r; asm("tanh.approx.f32 %0,%1;" : "=f"(r) : "f"(x)); return r;
}

// atan deg-9 minimax on [-1,1] (odd): atan(r) ~= r*(p0 + p1 s + p2 s^2 + p3 s^3 + p4 s^4)
#define AP0  0.9998660f
#define AP1 -0.3302995f
#define AP2  0.1801410f
#define AP3 -0.0851330f
#define AP4  0.0208351f

#define QPI     0.7853981633974483f    /* pi/4 */
#define HPI     1.5707963267948966f
#define UMAX    1.5663241850f          /* pi/2 - acos(1-1e-5) */
#define INV2PI  0.15915494309189535f

__global__ void __launch_bounds__(256, 8) contour_mask_kernel(
    const float* __restrict__ contour,   // [NCONT, KV, 2]
    float* __restrict__ out)             // [NCONT, MSIZE, MSIZE]
{
    __shared__ float4 sv[KV];   // prescaled (X, X, Y, Y)

    const int c = blockIdx.y;
    const int t = threadIdx.x;

    if (t < KV) {
        const float2 v = ((const float2*)contour)[c * KV + t];
        const float X = v.x * SQRTK;
        const float Y = v.y * SQRTK;
        sv[t] = make_float4(X, X, Y, Y);
    }
    __syncthreads();

    const int gid  = blockIdx.x * blockDim.x + t;     // 0 .. 32767
    const int pix0 = gid * 2;
    const float xs = (float)(pix0 >> 8)  * XSC;
    const float y0 = (float)(pix0 & 255) * XSC;
    const ull negyp = pk(-y0, -(y0 + XSC));

    const ull P0 = pk(AP0, AP0), P1 = pk(AP1, AP1), P2 = pk(AP2, AP2);
    const ull P3 = pk(AP3, AP3), P4 = pk(AP4, AP4);
    const ull MNEG1 = pk(-1.0f, -1.0f);
    const ull QP2   = pk(QPI, QPI);

    // k = 0 state
    float4 q0 = sv[0];
    ull DX2  = pk(q0.x - xs, q0.x - xs);
    ull NDX2 = f2mul(DX2, MNEG1);
    ull dyp  = f2add(pk(q0.z, q0.w), negyp);

    float S1a = 0.0f, Sta = 0.0f;    // pixel 0: sum t*cs, sum t
    float S1b = 0.0f, Stb = 0.0f;    // pixel 1

#pragma unroll 4
    for (int k = 0; k < KV; k++) {
        const int kn = (k + 1) & (KV - 1);
        const float4 q = sv[kn];                 // LDS.128
        const float rx = q.x - xs;
        const ull RX2  = pk(rx, rx);
        const ull NRX2 = f2mul(RX2, MNEG1);
        const ull ryp  = f2add(pk(q.z, q.w), negyp);

        const ull dotp = f2fma(DX2, RX2, f2mul(dyp, ryp));   // K*dot
        const ull crp  = f2fma(dyp, RX2, f2mul(NDX2, ryp));  // K*cross

        float cr0, cr1, d0, d1;
        upk(cr0, cr1, crp); upk(d0, d1, dotp);

        const float t0 = ftanh(cr0);             // == tanh(K*cross)
        const float t1 = ftanh(cr1);

        // r = (|cr| - |dot|) / (|cr| + |dot|)  in [-1, 1]
        const float num0 = fabsf(cr0) - fabsf(d0);
        const float num1 = fabsf(cr1) - fabsf(d1);
        const float den0 = fabsf(cr0) + fabsf(d0);
        const float den1 = fabsf(cr1) + fabsf(d1);
        const float r0 = num0 * frcp(den0);
        const float r1 = num1 * frcp(den1);

        // packed atan poly (odd): at = r * poly(r*r)
        const ull rp = pk(r0, r1);
        const ull s2 = f2mul(rp, rp);
        ull p = f2fma(s2, P4, P3);
        p = f2fma(p, s2, P2);
        p = f2fma(p, s2, P1);
        p = f2fma(p, s2, P0);
        const ull atp = f2mul(p, rp);
        const ull wp  = f2fma(atp, MNEG1, QP2);  // w = pi/4 - atan(r), w >= 0
        float w0, w1;
        upk(w0, w1, wp);

        const float u0 = fminf(w0, UMAX);
        const float u1 = fminf(w1, UMAX);

        // cs = copysign(u, dot);  angle = pi/2 - cs
        const float cs0 = __int_as_float(__float_as_int(u0) |
                                         (__float_as_int(d0) & 0x80000000u));
        const float cs1 = __int_as_float(__float_as_int(u1) |
                                         (__float_as_int(d1) & 0x80000000u));

        S1a = fmaf(t0, cs0, S1a);  Sta += t0;
        S1b = fmaf(t1, cs1, S1b);  Stb += t1;

        // rotate (register renames only)
        DX2 = RX2; NDX2 = NRX2; dyp = ryp;
    }

    float2 o;
    o.x = fminf(fabsf(fmaf(HPI, Sta, -S1a)) * INV2PI, 1.0f);
    o.y = fminf(fabsf(fmaf(HPI, Stb, -S1b)) * INV2PI, 1.0f);
    ((float2*)out)[c * (MSIZE * MSIZE / 2) + gid] = o;
}

extern "C" void kernel_launch(void* const* d_in, const int* in_sizes, int n_in,
                              void* d_out, int out_size)
{
    const float* contour = (const float*)d_in[0];
    float* out = (float*)d_out;

    dim3 grid((MSIZE * MSIZE) / (2 * 256), NCONT);   // 128 x 8 = 1024 blocks
    contour_mask_kernel<<<grid, 256>>>(contour, out);
}

// round 9
// speedup vs baseline: 1.0146x; 1.0146x over previous
#include <cuda_runtime.h>

// Contour_to_mask via winding angles.
// angle_k = acos(clip(dot/(|d||r|), ±(1-1e-5))) == clamp(atan2(|cr|,dot), A0, pi-A0)
// atan2(A,D), A,D>=0  ==  pi/4 + atan((A-D)/(A+D))   [exact rotation identity]
// => angle = pi/2 - copysign(min(pi/4 - atan(r), UMAX), dot)
// sign_k = tanh(K*cr);  out = min(|sum_k sign_k*angle_k|/2pi, 1)
//
// Coords prescaled by sqrt(K); 2 px/thread; fully packed f32x2 geometry
// (pixel x also packed); vertex LDS.128 software-pipelined 1 iter ahead.

#define MSIZE   256
#define KV      64
#define NCONT   8

#define SQRTK   316.2277660168379f
#define XSC     1.2352647109f          /* SQRTK / 256 */

typedef unsigned long long ull;

__device__ __forceinline__ ull pk(float lo, float hi) {
    ull r; asm("mov.b64 %0, {%1,%2};" : "=l"(r) : "f"(lo), "f"(hi)); return r;
}
__device__ __forceinline__ void upk(float& lo, float& hi, ull v) {
    asm("mov.b64 {%0,%1}, %2;" : "=f"(lo), "=f"(hi) : "l"(v));
}
__device__ __forceinline__ ull f2add(ull a, ull b) {
    ull d; asm("add.rn.f32x2 %0,%1,%2;" : "=l"(d) : "l"(a), "l"(b)); return d;
}
__device__ __forceinline__ ull f2mul(ull a, ull b) {
    ull d; asm("mul.rn.f32x2 %0,%1,%2;" : "=l"(d) : "l"(a), "l"(b)); return d;
}
__device__ __forceinline__ ull f2fma(ull a, ull b, ull c) {
    ull d; asm("fma.rn.f32x2 %0,%1,%2,%3;" : "=l"(d) : "l"(a), "l"(b), "l"(c)); return d;
}
__device__ __forceinline__ float frcp(float x) {
    float r; asm("rcp.approx.f32 %0,%1;" : "=f"(r) : "f"(x)); return r;
}
__device__ __forceinline__ float ftanh(float x) {
    float r; asm("tanh.approx.f32 %0,%1;" : "=f"(r) : "f"(x)); return r;
}

// atan deg-9 minimax on [-1,1] (odd): atan(r) ~= r*(p0 + p1 s + p2 s^2 + p3 s^3 + p4 s^4)
#define AP0  0.9998660f
#define AP1 -0.3302995f
#define AP2  0.1801410f
#define AP3 -0.0851330f
#define AP4  0.0208351f

#define QPI     0.7853981633974483f    /* pi/4 */
#define HPI     1.5707963267948966f
#define UMAX    1.5663241850f          /* pi/2 - acos(1-1e-5) */
#define INV2PI  0.15915494309189535f

__global__ void __launch_bounds__(256, 8) contour_mask_kernel(
    const float* __restrict__ contour,   // [NCONT, KV, 2]
    float* __restrict__ out)             // [NCONT, MSIZE, MSIZE]
{
    __shared__ float4 sv[KV];   // prescaled (X, X, Y, Y)

    const int c = blockIdx.y;
    const int t = threadIdx.x;

    if (t < KV) {
        const float2 v = ((const float2*)contour)[c * KV + t];
        const float X = v.x * SQRTK;
        const float Y = v.y * SQRTK;
        sv[t] = make_float4(X, X, Y, Y);
    }
    __syncthreads();

    const int gid  = blockIdx.x * blockDim.x + t;     // 0 .. 32767
    const int pix0 = gid * 2;
    const float xs = (float)(pix0 >> 8)  * XSC;
    const float y0 = (float)(pix0 & 255) * XSC;
    const ull negxp = pk(-xs, -xs);
    const ull negyp = pk(-y0, -(y0 + XSC));

    const ull P0 = pk(AP0, AP0), P1 = pk(AP1, AP1), P2 = pk(AP2, AP2);
    const ull P3 = pk(AP3, AP3), P4 = pk(AP4, AP4);
    const ull MNEG1 = pk(-1.0f, -1.0f);
    const ull QP2   = pk(QPI, QPI);

    // k = 0 state (dx/dy of current vertex) + prefetch of vertex 1
    float4 q0 = sv[0];
    ull dxp  = f2add(*(const ull*)&q0.x, negxp);
    ull ndxp = f2mul(dxp, MNEG1);
    ull dyp  = f2add(*(const ull*)&q0.z, negyp);
    float4 qn = sv[1];

    float S1a = 0.0f, Sta = 0.0f;    // pixel 0: sum t*cs, sum t
    float S1b = 0.0f, Stb = 0.0f;    // pixel 1

#pragma unroll 4
    for (int k = 0; k < KV; k++) {
        const float4 q = qn;                       // current next-vertex
        qn = sv[(k + 2) & (KV - 1)];               // prefetch (hides LDS latency)

        const ull rxp  = f2add(*(const ull*)&q.x, negxp);
        const ull nrxp = f2mul(rxp, MNEG1);
        const ull ryp  = f2add(*(const ull*)&q.z, negyp);

        const ull dotp = f2fma(dxp, rxp, f2mul(dyp, ryp));   // K*dot
        const ull crp  = f2fma(dyp, rxp, f2mul(ndxp, ryp));  // K*cross

        float cr0, cr1, d0, d1;
        upk(cr0, cr1, crp); upk(d0, d1, dotp);

        const float t0 = ftanh(cr0);               // == tanh(K*cross)
        const float t1 = ftanh(cr1);

        // r = (|cr| - |dot|) / (|cr| + |dot|)  in [-1, 1]
        const float num0 = fabsf(cr0) - fabsf(d0);
        const float num1 = fabsf(cr1) - fabsf(d1);
        const float den0 = fabsf(cr0) + fabsf(d0);
        const float den1 = fabsf(cr1) + fabsf(d1);
        const float r0 = num0 * frcp(den0);
        const float r1 = num1 * frcp(den1);

        // packed atan poly (odd): at = r * poly(r*r)
        const ull rp = pk(r0, r1);
        const ull s2 = f2mul(rp, rp);
        ull p = f2fma(s2, P4, P3);
        p = f2fma(p, s2, P2);
        p = f2fma(p, s2, P1);
        p = f2fma(p, s2, P0);
        const ull atp = f2mul(p, rp);
        const ull wp  = f2fma(atp, MNEG1, QP2);    // w = pi/4 - atan(r) >= 0
        float w0, w1;
        upk(w0, w1, wp);

        const float u0 = fminf(w0, UMAX);
        const float u1 = fminf(w1, UMAX);

        // cs = copysign(u, dot);  angle = pi/2 - cs
        const float cs0 = __int_as_float(__float_as_int(u0) |
                                         (__float_as_int(d0) & 0x80000000u));
        const float cs1 = __int_as_float(__float_as_int(u1) |
                                         (__float_as_int(d1) & 0x80000000u));

        S1a = fmaf(t0, cs0, S1a);  Sta += t0;
        S1b = fmaf(t1, cs1, S1b);  Stb += t1;

        // rotate (register renames only)
        dxp = rxp; ndxp = nrxp; dyp = ryp;
    }

    float2 o;
    o.x = fminf(fabsf(fmaf(HPI, Sta, -S1a)) * INV2PI, 1.0f);
    o.y = fminf(fabsf(fmaf(HPI, Stb, -S1b)) * INV2PI, 1.0f);
    ((float2*)out)[c * (MSIZE * MSIZE / 2) + gid] = o;
}

extern "C" void kernel_launch(void* const* d_in, const int* in_sizes, int n_in,
                              void* d_out, int out_size)
{
    const float* contour = (const float*)d_in[0];
    float* out = (float*)d_out;

    dim3 grid((MSIZE * MSIZE) / (2 * 256), NCONT);   // 128 x 8 = 1024 blocks
    contour_mask_kernel<<<grid, 256>>>(contour, out);
}

// round 10
// speedup vs baseline: 1.0611x; 1.0458x over previous
#include <cuda_runtime.h>

// Contour_to_mask via winding angles.
// angle_k = acos(clip(dot/(|d||r|), ±(1-1e-5))) == clamp(atan2(|cr|,dot), A0, pi-A0)
// atan2(A,D), A,D>=0  ==  pi/4 + atan((A-D)/(A+D))   [exact rotation identity]
// => angle = pi/2 - copysign(min(pi/4 - atan(r), UMAX), dot)
// sign_k = tanh(K*cr);  out = min(|sum_k sign_k*angle_k|/2pi, 1)
//
// Coords prescaled by sqrt(K). 4 px/thread (two packed f32x2 pairs, same row):
// vertex LDS.128, rx prep and dx*rx shared across all 4 pixels; the two pair
// chains are independent -> 2x ILP per warp. 128-thd blocks, 8 blocks/SM.

#define MSIZE   256
#define KV      64
#define NCONT   8

#define SQRTK   316.2277660168379f
#define XSC     1.2352647109f          /* SQRTK / 256 */

typedef unsigned long long ull;

__device__ __forceinline__ ull pk(float lo, float hi) {
    ull r; asm("mov.b64 %0, {%1,%2};" : "=l"(r) : "f"(lo), "f"(hi)); return r;
}
__device__ __forceinline__ void upk(float& lo, float& hi, ull v) {
    asm("mov.b64 {%0,%1}, %2;" : "=f"(lo), "=f"(hi) : "l"(v));
}
__device__ __forceinline__ ull f2add(ull a, ull b) {
    ull d; asm("add.rn.f32x2 %0,%1,%2;" : "=l"(d) : "l"(a), "l"(b)); return d;
}
__device__ __forceinline__ ull f2mul(ull a, ull b) {
    ull d; asm("mul.rn.f32x2 %0,%1,%2;" : "=l"(d) : "l"(a), "l"(b)); return d;
}
__device__ __forceinline__ ull f2fma(ull a, ull b, ull c) {
    ull d; asm("fma.rn.f32x2 %0,%1,%2,%3;" : "=l"(d) : "l"(a), "l"(b), "l"(c)); return d;
}
__device__ __forceinline__ float frcp(float x) {
    float r; asm("rcp.approx.f32 %0,%1;" : "=f"(r) : "f"(x)); return r;
}
__device__ __forceinline__ float ftanh(float x) {
    float r; asm("tanh.approx.f32 %0,%1;" : "=f"(r) : "f"(x)); return r;
}

// atan deg-9 minimax on [-1,1] (odd): atan(r) ~= r*(p0 + p1 s + p2 s^2 + p3 s^3 + p4 s^4)
#define AP0  0.9998660f
#define AP1 -0.3302995f
#define AP2  0.1801410f
#define AP3 -0.0851330f
#define AP4  0.0208351f

#define QPI     0.7853981633974483f    /* pi/4 */
#define HPI     1.5707963267948966f
#define UMAX    1.5663241850f          /* pi/2 - acos(1-1e-5) */
#define INV2PI  0.15915494309189535f

__global__ void __launch_bounds__(128, 8) contour_mask_kernel(
    const float* __restrict__ contour,   // [NCONT, KV, 2]
    float* __restrict__ out)             // [NCONT, MSIZE, MSIZE]
{
    __shared__ float4 sv[KV];   // prescaled (X, X, Y, Y)

    const int c = blockIdx.y;
    const int t = threadIdx.x;

    if (t < KV) {
        const float2 v = ((const float2*)contour)[c * KV + t];
        const float X = v.x * SQRTK;
        const float Y = v.y * SQRTK;
        sv[t] = make_float4(X, X, Y, Y);
    }
    __syncthreads();

    const int gid  = blockIdx.x * blockDim.x + t;     // 0 .. 16383
    const int pix0 = gid * 4;
    const float xs = (float)(pix0 >> 8)  * XSC;
    const float yb = (float)(pix0 & 255) * XSC;
    const ull negxp  = pk(-xs, -xs);
    const ull negy01 = pk(-yb, -(yb + XSC));
    const ull negy23 = pk(-(yb + 2.0f * XSC), -(yb + 3.0f * XSC));

    const ull P0 = pk(AP0, AP0), P1 = pk(AP1, AP1), P2 = pk(AP2, AP2);
    const ull P3 = pk(AP3, AP3), P4 = pk(AP4, AP4);
    const ull MNEG1 = pk(-1.0f, -1.0f);
    const ull QP2   = pk(QPI, QPI);

    // k = 0 state
    float4 q0 = sv[0];
    ull dxp  = f2add(*(const ull*)&q0.x, negxp);
    ull ndxp = f2mul(dxp, MNEG1);
    ull dy01 = f2add(*(const ull*)&q0.z, negy01);
    ull dy23 = f2add(*(const ull*)&q0.z, negy23);

    float S1[4] = {0.f, 0.f, 0.f, 0.f};   // sum t*cs per pixel
    float St[4] = {0.f, 0.f, 0.f, 0.f};   // sum t per pixel

#pragma unroll 4
    for (int k = 0; k < KV; k++) {
        const int kn = (k + 1) & (KV - 1);
        const float4 q = sv[kn];                    // LDS.128 broadcast
        const ull rxp  = f2add(*(const ull*)&q.x, negxp);
        const ull nrxp = f2mul(rxp, MNEG1);
        const ull ry01 = f2add(*(const ull*)&q.z, negy01);
        const ull ry23 = f2add(*(const ull*)&q.z, negy23);

        const ull drs  = f2mul(dxp, rxp);           // (dx*rx, dx*rx)

        const ull dot01 = f2fma(dy01, ry01, drs);
        const ull dot23 = f2fma(dy23, ry23, drs);
        const ull cr01  = f2fma(dy01, rxp, f2mul(ndxp, ry01));
        const ull cr23  = f2fma(dy23, rxp, f2mul(ndxp, ry23));

        float cr[4], dd[4];
        upk(cr[0], cr[1], cr01); upk(cr[2], cr[3], cr23);
        upk(dd[0], dd[1], dot01); upk(dd[2], dd[3], dot23);

        float rr[4], tt[4];
#pragma unroll
        for (int j = 0; j < 4; j++) {
            tt[j] = ftanh(cr[j]);                    // == tanh(K*cross)
            const float num = fabsf(cr[j]) - fabsf(dd[j]);
            const float den = fabsf(cr[j]) + fabsf(dd[j]);
            rr[j] = num * frcp(den);                 // in [-1, 1]
        }

        // packed atan poly (odd): at = r * poly(r*r); w = pi/4 - at >= 0
        const ull r01 = pk(rr[0], rr[1]);
        const ull r23 = pk(rr[2], rr[3]);
        const ull s01 = f2mul(r01, r01);
        const ull s23 = f2mul(r23, r23);
        ull p01 = f2fma(s01, P4, P3);
        ull p23 = f2fma(s23, P4, P3);
        p01 = f2fma(p01, s01, P2);  p23 = f2fma(p23, s23, P2);
        p01 = f2fma(p01, s01, P1);  p23 = f2fma(p23, s23, P1);
        p01 = f2fma(p01, s01, P0);  p23 = f2fma(p23, s23, P0);
        const ull at01 = f2mul(p01, r01);
        const ull at23 = f2mul(p23, r23);
        const ull w01 = f2fma(at01, MNEG1, QP2);
        const ull w23 = f2fma(at23, MNEG1, QP2);

        float ww[4];
        upk(ww[0], ww[1], w01); upk(ww[2], ww[3], w23);

#pragma unroll
        for (int j = 0; j < 4; j++) {
            const float u = fminf(ww[j], UMAX);
            const float cs = __int_as_float(__float_as_int(u) |
                                            (__float_as_int(dd[j]) & 0x80000000u));
            S1[j] = fmaf(tt[j], cs, S1[j]);
            St[j] += tt[j];
        }

        // rotate (register renames only)
        dxp = rxp; ndxp = nrxp; dy01 = ry01; dy23 = ry23;
    }

    float4 o;
    o.x = fminf(fabsf(fmaf(HPI, St[0], -S1[0])) * INV2PI, 1.0f);
    o.y = fminf(fabsf(fmaf(HPI, St[1], -S1[1])) * INV2PI, 1.0f);
    o.z = fminf(fabsf(fmaf(HPI, St[2], -S1[2])) * INV2PI, 1.0f);
    o.w = fminf(fabsf(fmaf(HPI, St[3], -S1[3])) * INV2PI, 1.0f);
    ((float4*)out)[c * (MSIZE * MSIZE / 4) + gid] = o;
}

extern "C" void kernel_launch(void* const* d_in, const int* in_sizes, int n_in,
                              void* d_out, int out_size)
{
    const float* contour = (const float*)d_in[0];
    float* out = (float*)d_out;

    dim3 grid((MSIZE * MSIZE) / (4 * 128), NCONT);   // 128 x 8 = 1024 blocks
    contour_mask_kernel<<<grid, 128>>>(contour, out);
}